// round 8
// baseline (speedup 1.0000x reference)
#include <cuda_runtime.h>
#include <cuda_bf16.h>
#include <math.h>
#include <stdint.h>

#define BSZ  2
#define SEQ  1024
#define DM   1024
#define NH   16
#define HDIM 64
#define NL   4
#define VOC  32000
#define NFR  50
#define DLAT 512
#define ROWS (BSZ*SEQ)   // 2048
#define KT   16

// ---------------- scratch (device globals; no allocation allowed) ----------
__device__ float g_h   [ROWS*DM];
__device__ float g_kv  [ROWS*DM];          // tmp (embed base) / attention out
__device__ float g_qkv [ROWS*3*DM];        // fused q|k|v
__device__ float g_krvr[ROWS*2*DM];        // fused kr|vr
__device__ float g_lat [ROWS*DLAT];
__device__ float g_four[ROWS*NFR];
__device__ float g_sc[(size_t)BSZ*NH*SEQ*SEQ];   // 134 MB score tensor

// split weights, n-major [N][K] bf16 hi/lo (transposed)
#define WSZ_DD   (1024*1024)
#define WSZ_HALF (512*1024)
#define LSTRIDE  (4*WSZ_DD + 3*WSZ_HALF)
#define OFF_RULE 0
#define OFF_L(l) ((size_t)WSZ_DD + (size_t)(l)*LSTRIDE)
#define LOFF_QKV  0
#define LOFF_DOWN (3*(size_t)WSZ_DD)
#define LOFF_UP   (3*(size_t)WSZ_DD + WSZ_HALF)
#define LOFF_WO   (3*(size_t)WSZ_DD + 3*(size_t)WSZ_HALF)
#define OFF_WOUT ((size_t)WSZ_DD + 4*(size_t)LSTRIDE)
#define WTOT     (OFF_WOUT + (size_t)VOC*DM)
__device__ __align__(16) __nv_bfloat16 g_wbh[WTOT];
__device__ __align__(16) __nv_bfloat16 g_wbl[WTOT];

// ---------------- f32x2 packed helpers (Blackwell FFMA2) -------------------
__device__ __forceinline__ unsigned long long pk2(float lo, float hi) {
    unsigned long long r;
    asm("mov.b64 %0, {%1, %2};" : "=l"(r) : "f"(lo), "f"(hi));
    return r;
}
__device__ __forceinline__ unsigned long long ffma2(
    unsigned long long a, unsigned long long b, unsigned long long c) {
    unsigned long long d;
    asm("fma.rn.f32x2 %0, %1, %2, %3;" : "=l"(d) : "l"(a), "l"(b), "l"(c));
    return d;
}
__device__ __forceinline__ float2 up2(unsigned long long v) {
    float2 f;
    asm("mov.b64 {%0, %1}, %2;" : "=f"(f.x), "=f"(f.y) : "l"(v));
    return f;
}

// ---------------- misc helpers ---------------------------------------------
__device__ __forceinline__ uint32_t smem_to_u32(const void* p) {
    uint32_t a;
    asm("{ .reg .u64 t; cvta.to.shared.u64 t, %1; cvt.u32.u64 %0, t; }" : "=r"(a) : "l"(p));
    return a;
}
// bf16x2 pack: low half = bf16(lo), high half = bf16(hi)
__device__ __forceinline__ uint32_t bfpack(float lo, float hi) {
    uint32_t r;
    asm("cvt.rn.bf16x2.f32 %0, %1, %2;" : "=r"(r) : "f"(hi), "f"(lo));
    return r;
}
__device__ __forceinline__ float bflo(uint32_t p) { return __uint_as_float(p << 16); }
__device__ __forceinline__ float bfhi(uint32_t p) { return __uint_as_float(p & 0xffff0000u); }
#define STS128(addr, a, b, c, d) \
    asm volatile("st.shared.v4.b32 [%0], {%1, %2, %3, %4};" \
        :: "r"(addr), "r"(a), "r"(b), "r"(c), "r"(d) : "memory")
#define LDSM_X4(r0, r1, r2, r3, addr) \
    asm volatile("ldmatrix.sync.aligned.m8n8.x4.shared.b16 {%0,%1,%2,%3}, [%4];" \
        : "=r"(r0), "=r"(r1), "=r"(r2), "=r"(r3) : "r"(addr))
#define LDSM_X2(r0, r1, addr) \
    asm volatile("ldmatrix.sync.aligned.m8n8.x2.shared.b16 {%0,%1}, [%2];" \
        : "=r"(r0), "=r"(r1) : "r"(addr))
#define MMA16816(d, a0, a1, a2, a3, b0, b1) \
    asm volatile("mma.sync.aligned.m16n8k16.row.col.f32.bf16.bf16.f32 " \
        "{%0,%1,%2,%3}, {%4,%5,%6,%7}, {%8,%9}, {%0,%1,%2,%3};" \
        : "+f"((d)[0]), "+f"((d)[1]), "+f"((d)[2]), "+f"((d)[3]) \
        : "r"(a0), "r"(a1), "r"(a2), "r"(a3), "r"(b0), "r"(b1))

// ===== weight transpose + bf16 split, vectorized stores: W[K,N] -> T[N,K] ==
__global__ __launch_bounds__(256) void wsplit_k(
    const float* __restrict__ W, int K, int N,
    __nv_bfloat16* __restrict__ Th, __nv_bfloat16* __restrict__ Tl)
{
    __shared__ float t[32][33];
    const int k0 = blockIdx.y * 32, n0 = blockIdx.x * 32;
    const int tx = threadIdx.x, ty = threadIdx.y;   // (32,8)
    const int tid = ty * 32 + tx;
#pragma unroll
    for (int i = 0; i < 4; i++)
        t[ty + 8 * i][tx] = W[(size_t)(k0 + ty + 8 * i) * N + n0 + tx];
    __syncthreads();
    // 256 threads: 128 write hi (half=0), 128 write lo (half=1).
    const int half = tid >> 7;
    const int r = tid & 127;
    const int nl = r >> 2;          // 0..31
    const int kg = r & 3;           // 0..3  -> k run of 8
    uint32_t h[4], l[4];
#pragma unroll
    for (int i = 0; i < 4; i++) {
        float x0 = t[kg * 8 + 2 * i][nl];
        float x1 = t[kg * 8 + 2 * i + 1][nl];
        uint32_t hp = bfpack(x0, x1);
        uint32_t lp = bfpack(x0 - bflo(hp), x1 - bfhi(hp));
        h[i] = hp; l[i] = lp;
    }
    size_t o = (size_t)(n0 + nl) * K + k0 + kg * 8;
    if (half == 0) *(uint4*)(Th + o) = make_uint4(h[0], h[1], h[2], h[3]);
    else           *(uint4*)(Tl + o) = make_uint4(l[0], l[1], l[2], l[3]);
}

// ================= HMMA bf16-split GEMM (n-major B, non-trans ldmatrix) ====
// C[M,*] = (A [+A2])[M,K](fp32, row stride lda) * B, with Bt = W^T bf16 hi/lo
// [N][K]. BM = MT*32 (MT=4 -> 128, MT=2 -> 64), BN=128, BK=32. 256 threads.
#define ASTR 40   // bf16 elems per smem row (80 B)

template<int MT>
__global__ __launch_bounds__(256) void gemm_mma(
    int M, int K, int lda,
    const float* __restrict__ A, const float* __restrict__ A2,
    const __nv_bfloat16* __restrict__ Bh, const __nv_bfloat16* __restrict__ Bl,
    const float* __restrict__ bias, float* __restrict__ C, int ldc)
{
    constexpr int BM = MT * 32;
    constexpr int TPR = 256 / BM;           // threads per A row
    constexpr int FPT = 32 / TPR;           // floats per thread (16 or 8)
    constexpr int ATILEB = BM * 80;
    constexpr int BTILEB = 128 * 80;
    constexpr int OAH = 0, OAL = ATILEB, OBH = 2 * ATILEB, OBL = 2 * ATILEB + BTILEB;
    constexpr int BUFSTR = 2 * ATILEB + 2 * BTILEB;

    extern __shared__ char smem[];
    const uint32_t sb = smem_to_u32(smem);
    const int tid = threadIdx.x, lane = tid & 31, wid = tid >> 5;
    const int brow = blockIdx.y * BM, bcol = blockIdx.x * 128;
    const int wm = wid & 1, wn = wid >> 1;          // 2 x 4 warp grid

    const int lrow = tid / TPR, lseg = tid % TPR;
    const float* Ap  = A + (size_t)(brow + lrow) * lda + lseg * FPT;
    const float* A2p = A2 ? A2 + (size_t)(brow + lrow) * lda + lseg * FPT : (const float*)0;
    const uint32_t asoff = (uint32_t)(lrow * ASTR + lseg * FPT) * 2;

    const int brw2 = tid >> 1, bseg = tid & 1;
    const __nv_bfloat16* Bhp = Bh + (size_t)(bcol + brw2) * K + bseg * 16;
    const __nv_bfloat16* Blp = Bl + (size_t)(bcol + brw2) * K + bseg * 16;
    const uint32_t bsoff = (uint32_t)(brw2 * ASTR + bseg * 16) * 2;

    float acc[MT][4][4];
#pragma unroll
    for (int i = 0; i < MT; i++)
#pragma unroll
        for (int j = 0; j < 4; j++)
#pragma unroll
            for (int e = 0; e < 4; e++) acc[i][j][e] = 0.f;

    float4 pa[FPT / 4]; uint4 pbh[2], pbl[2];

#define LOADG(k0) do { \
    _Pragma("unroll") \
    for (int i = 0; i < FPT / 4; i++) { \
        pa[i] = *(const float4*)(Ap + (k0) + i * 4); \
        if (A2p) { \
            float4 y = *(const float4*)(A2p + (k0) + i * 4); \
            pa[i].x += y.x; pa[i].y += y.y; pa[i].z += y.z; pa[i].w += y.w; \
        } \
    } \
    pbh[0] = *(const uint4*)(Bhp + (k0));  pbh[1] = *(const uint4*)(Bhp + (k0) + 8); \
    pbl[0] = *(const uint4*)(Blp + (k0));  pbl[1] = *(const uint4*)(Blp + (k0) + 8); \
} while (0)

#define STOREBUF(b) do { \
    uint32_t hh[FPT / 2], ll[FPT / 2]; \
    _Pragma("unroll") \
    for (int i = 0; i < FPT / 4; i++) { \
        float4 x = pa[i]; \
        uint32_t h0 = bfpack(x.x, x.y), h1 = bfpack(x.z, x.w); \
        uint32_t l0 = bfpack(x.x - bflo(h0), x.y - bfhi(h0)); \
        uint32_t l1 = bfpack(x.z - bflo(h1), x.w - bfhi(h1)); \
        hh[2*i] = h0; hh[2*i+1] = h1; ll[2*i] = l0; ll[2*i+1] = l1; \
    } \
    uint32_t base_ = sb + (uint32_t)(b) * BUFSTR; \
    _Pragma("unroll") \
    for (int i = 0; i < FPT / 8; i++) { \
        STS128(base_ + OAH + asoff + i * 16, hh[4*i], hh[4*i+1], hh[4*i+2], hh[4*i+3]); \
        STS128(base_ + OAL + asoff + i * 16, ll[4*i], ll[4*i+1], ll[4*i+2], ll[4*i+3]); \
    } \
    STS128(base_ + OBH + bsoff,      pbh[0].x, pbh[0].y, pbh[0].z, pbh[0].w); \
    STS128(base_ + OBH + bsoff + 16, pbh[1].x, pbh[1].y, pbh[1].z, pbh[1].w); \
    STS128(base_ + OBL + bsoff,      pbl[0].x, pbl[0].y, pbl[0].z, pbl[0].w); \
    STS128(base_ + OBL + bsoff + 16, pbl[1].x, pbl[1].y, pbl[1].z, pbl[1].w); \
} while (0)

    const int nchunk = K / 32;
    LOADG(0);
    STOREBUF(0);
    __syncthreads();

    const uint32_t arow = (uint32_t)(wm * (MT * 16) + (lane & 15));
    const uint32_t acol = (uint32_t)((lane >> 4) * 8);
    const uint32_t brw  = (uint32_t)(wn * 32 + (lane & 7));
    const uint32_t bcl  = (uint32_t)(((lane >> 3) & 1) * 8);

    int buf = 0;
    for (int ck = 0; ck < nchunk; ck++) {
        if (ck + 1 < nchunk) LOADG((ck + 1) * 32);

        const uint32_t base = sb + (uint32_t)buf * BUFSTR;
#pragma unroll
        for (int ks = 0; ks < 2; ks++) {
            uint32_t ah[MT][4], al[MT][4];
#pragma unroll
            for (int mt = 0; mt < MT; mt++) {
                uint32_t aoff = ((arow + mt * 16) * ASTR + acol + ks * 16) * 2;
                LDSM_X4(ah[mt][0], ah[mt][1], ah[mt][2], ah[mt][3], base + OAH + aoff);
                LDSM_X4(al[mt][0], al[mt][1], al[mt][2], al[mt][3], base + OAL + aoff);
            }
#pragma unroll
            for (int nt = 0; nt < 4; nt++) {
                uint32_t boff = ((brw + nt * 8) * ASTR + bcl + ks * 16) * 2;
                uint32_t bh0, bh1, bl0, bl1;
                LDSM_X2(bh0, bh1, base + OBH + boff);
                LDSM_X2(bl0, bl1, base + OBL + boff);
#pragma unroll
                for (int mt = 0; mt < MT; mt++) {
                    MMA16816(acc[mt][nt], ah[mt][0], ah[mt][1], ah[mt][2], ah[mt][3], bh0, bh1);
                    MMA16816(acc[mt][nt], ah[mt][0], ah[mt][1], ah[mt][2], ah[mt][3], bl0, bl1);
                    MMA16816(acc[mt][nt], al[mt][0], al[mt][1], al[mt][2], al[mt][3], bh0, bh1);
                }
            }
        }
        if (ck + 1 < nchunk) STOREBUF(buf ^ 1);
        __syncthreads();
        buf ^= 1;
    }

    // ---- epilogue ----
#pragma unroll
    for (int mt = 0; mt < MT; mt++) {
        int r0 = brow + wm * (MT * 16) + mt * 16 + (lane >> 2);
#pragma unroll
        for (int nt = 0; nt < 4; nt++) {
            int c = bcol + wn * 32 + nt * 8 + (lane & 3) * 2;
            float bx = 0.f, by = 0.f;
            if (bias) { bx = bias[c]; by = bias[c + 1]; }
            float2 o0, o1;
            o0.x = acc[mt][nt][0] + bx; o0.y = acc[mt][nt][1] + by;
            o1.x = acc[mt][nt][2] + bx; o1.y = acc[mt][nt][3] + by;
            *(float2*)(C + (size_t)r0 * ldc + c)       = o0;
            *(float2*)(C + (size_t)(r0 + 8) * ldc + c) = o1;
        }
    }
#undef LOADG
#undef STOREBUF
}

#define DSM4 (2*(2*(128*80) + 2*(128*80)))   // 81920
#define DSM2 (2*(2*(64*80)  + 2*(128*80)))   // 61440

// ---------------- FFMA2 SGEMM (kept for the K=50 embedding GEMM) -----------
__global__ __launch_bounds__(256) void sgemm2_k(
    int M, int N, int K,
    const float* __restrict__ A, const float* __restrict__ B,
    const float* __restrict__ bias, float* __restrict__ C)
{
    __shared__ __align__(16) float As[KT][128];
    __shared__ __align__(16) float Bs[KT][128];
    const int tid  = threadIdx.x;
    const int brow = blockIdx.y * 128;
    const int bcol = blockIdx.x * 128;
    const int ty = tid >> 4, tx = tid & 15;
    const int ar = tid >> 1, aks = (tid & 1) * 8;

    unsigned long long acc[8][4];
#pragma unroll
    for (int i = 0; i < 8; i++)
#pragma unroll
        for (int j = 0; j < 4; j++) acc[i][j] = 0ULL;

    for (int k0 = 0; k0 < K; k0 += KT) {
#pragma unroll
        for (int i = 0; i < 8; i++) {
            int kk = aks + i;
            As[kk][ar] = (k0 + kk < K) ? A[(size_t)(brow + ar) * K + k0 + kk] : 0.f;
        }
#pragma unroll
        for (int p = 0; p < 2; p++) {
            int id = p * 256 + tid;
            int kk = id >> 5, c4 = (id & 31) * 4;
            float4 bv = make_float4(0.f, 0.f, 0.f, 0.f);
            if (k0 + kk < K) bv = *(const float4*)(B + (size_t)(k0 + kk) * N + bcol + c4);
            *(float4*)&Bs[kk][c4] = bv;
        }
        __syncthreads();
#pragma unroll
        for (int kk = 0; kk < KT; kk++) {
            float4 a0 = *(const float4*)&As[kk][ty * 4];
            float4 a1 = *(const float4*)&As[kk][64 + ty * 4];
            float4 b0 = *(const float4*)&Bs[kk][tx * 4];
            float4 b1 = *(const float4*)&Bs[kk][64 + tx * 4];
            unsigned long long rb[4] = { pk2(b0.x, b0.y), pk2(b0.z, b0.w),
                                         pk2(b1.x, b1.y), pk2(b1.z, b1.w) };
            float ra[8] = { a0.x, a0.y, a0.z, a0.w, a1.x, a1.y, a1.z, a1.w };
#pragma unroll
            for (int i = 0; i < 8; i++) {
                unsigned long long ad = pk2(ra[i], ra[i]);
#pragma unroll
                for (int j = 0; j < 4; j++) acc[i][j] = ffma2(ad, rb[j], acc[i][j]);
            }
        }
        __syncthreads();
    }
#pragma unroll
    for (int ih = 0; ih < 2; ih++)
#pragma unroll
    for (int ii = 0; ii < 4; ii++) {
        int i = ih * 4 + ii;
        int r = brow + ih * 64 + ty * 4 + ii;
#pragma unroll
        for (int jh = 0; jh < 2; jh++) {
            int c = bcol + jh * 64 + tx * 4;
            float2 p0 = up2(acc[i][jh * 2]);
            float2 p1 = up2(acc[i][jh * 2 + 1]);
            float4 o; o.x = p0.x; o.y = p0.y; o.z = p1.x; o.w = p1.y;
            if (bias) { o.x += bias[c]; o.y += bias[c+1]; o.z += bias[c+2]; o.w += bias[c+3]; }
            *(float4*)(C + (size_t)r * N + c) = o;
        }
    }
}

// ---------------- Fourier token features -----------------------------------
__global__ void fourier_k(const int* __restrict__ src, const float* __restrict__ a_n,
                          const float* __restrict__ b_n, float* __restrict__ F)
{
    int idx = blockIdx.x * blockDim.x + threadIdx.x;
    if (idx >= ROWS * NFR) return;
    int bs = idx / NFR, n = idx % NFR;
    int tok = src[bs];
    float x   = (float)tok * (1.0f / (float)VOC);
    float ang = 6.28318530717958647692f * (float)(n + 1) * x;
    F[idx] = a_n[tok * NFR + n] * cosf(ang) + b_n[tok * NFR + n] * sinf(ang);
}

// ---------------- h += sinusoidal PE ---------------------------------------
__global__ void addpe_k(float* __restrict__ h)
{
    int idx = blockIdx.x * blockDim.x + threadIdx.x;
    if (idx >= ROWS * DM) return;
    int d = idx & (DM - 1);
    int s = (idx / DM) & (SEQ - 1);
    float div = expf(-(float)(d & ~1) * 8.99447301948846e-3f);
    float ang = (float)s * div;
    h[idx] += (d & 1) ? cosf(ang) : sinf(ang);
}

// ---------------- scores: Sc[bh,i,j] = (q.k/32) * exp(-0.01|i-j|) ----------
__global__ __launch_bounds__(256) void scores_k(
    const float* __restrict__ Q, int ldq,
    const float* __restrict__ Kc, int ldk, float* __restrict__ Sc)
{
    const int bh = blockIdx.z;
    const int b  = bh >> 4, h = bh & 15;
    const int i0 = blockIdx.y * 64, j0 = blockIdx.x * 64;
    __shared__ __align__(16) float qs[64][68];
    __shared__ __align__(16) float ks[64][68];
    const int tid = threadIdx.x;
#pragma unroll
    for (int p = 0; p < 16; p++) {
        int idx = p * 256 + tid;
        int r = idx >> 6, c = idx & 63;
        qs[c][r] = Q [(size_t)(b * SEQ + i0 + r) * ldq + h * HDIM + c];
        ks[c][r] = Kc[(size_t)(b * SEQ + j0 + r) * ldk + h * HDIM + c];
    }
    __syncthreads();
    const int ty = tid >> 4, tx = tid & 15;
    unsigned long long acc[4][2];
#pragma unroll
    for (int i = 0; i < 4; i++) { acc[i][0] = 0ULL; acc[i][1] = 0ULL; }
#pragma unroll
    for (int d = 0; d < 64; d++) {
        float4 rb4 = *(const float4*)&ks[d][tx * 4];
        float4 ra4 = *(const float4*)&qs[d][ty * 4];
        unsigned long long rb[2] = { pk2(rb4.x, rb4.y), pk2(rb4.z, rb4.w) };
        float ra[4] = { ra4.x, ra4.y, ra4.z, ra4.w };
#pragma unroll
        for (int ii = 0; ii < 4; ii++) {
            unsigned long long ad = pk2(ra[ii], ra[ii]);
            acc[ii][0] = ffma2(ad, rb[0], acc[ii][0]);
            acc[ii][1] = ffma2(ad, rb[1], acc[ii][1]);
        }
    }
    const float scale = 0.03125f;
#pragma unroll
    for (int ii = 0; ii < 4; ii++) {
        int gi = i0 + ty * 4 + ii;
        int gj = j0 + tx * 4;
        float2 p0 = up2(acc[ii][0]), p1 = up2(acc[ii][1]);
        float4 o;
        o.x = p0.x * scale * expf(-0.01f * fabsf((float)(gi - gj)));
        o.y = p0.y * scale * expf(-0.01f * fabsf((float)(gi - gj - 1)));
        o.z = p1.x * scale * expf(-0.01f * fabsf((float)(gi - gj - 2)));
        o.w = p1.y * scale * expf(-0.01f * fabsf((float)(gi - gj - 3)));
        *(float4*)(Sc + ((size_t)bh * SEQ + gi) * SEQ + gj) = o;
    }
}

// ---------------- row softmax ----------------------------------------------
__global__ __launch_bounds__(256) void softmax_k(float* __restrict__ Sc)
{
    __shared__ float red[256];
    float* p = Sc + (size_t)blockIdx.x * SEQ;
    const int t = threadIdx.x;
    float v0 = p[t], v1 = p[t + 256], v2 = p[t + 512], v3 = p[t + 768];
    float mx = fmaxf(fmaxf(v0, v1), fmaxf(v2, v3));
    red[t] = mx; __syncthreads();
    for (int s = 128; s > 0; s >>= 1) { if (t < s) red[t] = fmaxf(red[t], red[t + s]); __syncthreads(); }
    mx = red[0]; __syncthreads();
    v0 = expf(v0 - mx); v1 = expf(v1 - mx); v2 = expf(v2 - mx); v3 = expf(v3 - mx);
    float sm = v0 + v1 + v2 + v3;
    red[t] = sm; __syncthreads();
    for (int s = 128; s > 0; s >>= 1) { if (t < s) red[t] += red[t + s]; __syncthreads(); }
    float inv = 1.0f / red[0];
    p[t] = v0 * inv; p[t + 256] = v1 * inv; p[t + 512] = v2 * inv; p[t + 768] = v3 * inv;
}

// ---------------- attn @ V --------------------------------------------------
__global__ __launch_bounds__(256) void av_k(
    const float* __restrict__ P, const float* __restrict__ Vc, int ldv,
    float* __restrict__ O)
{
    const int bh = blockIdx.y;
    const int b  = bh >> 4, h = bh & 15;
    const int i0 = blockIdx.x * 64;
    __shared__ __align__(16) float ps[64][68];
    __shared__ __align__(16) float vs[64][68];
    const int tid = threadIdx.x;
    const int ty = tid >> 4, tx = tid & 15;
    unsigned long long acc[4][2];
#pragma unroll
    for (int i = 0; i < 4; i++) { acc[i][0] = 0ULL; acc[i][1] = 0ULL; }

    for (int jt = 0; jt < SEQ / 64; jt++) {
#pragma unroll
        for (int p = 0; p < 16; p++) {
            int idx = p * 256 + tid;
            int r = idx >> 6, c = idx & 63;
            ps[c][r] = P [((size_t)bh * SEQ + i0 + r) * SEQ + jt * 64 + c];
            vs[r][c] = Vc[(size_t)(b * SEQ + jt * 64 + r) * ldv + h * HDIM + c];
        }
        __syncthreads();
#pragma unroll
        for (int jj = 0; jj < 64; jj++) {
            float4 rb4 = *(const float4*)&vs[jj][tx * 4];
            float4 ra4 = *(const float4*)&ps[jj][ty * 4];
            unsigned long long rb[2] = { pk2(rb4.x, rb4.y), pk2(rb4.z, rb4.w) };
            float ra[4] = { ra4.x, ra4.y, ra4.z, ra4.w };
#pragma unroll
            for (int ii = 0; ii < 4; ii++) {
                unsigned long long ad = pk2(ra[ii], ra[ii]);
                acc[ii][0] = ffma2(ad, rb[0], acc[ii][0]);
                acc[ii][1] = ffma2(ad, rb[1], acc[ii][1]);
            }
        }
        __syncthreads();
    }
#pragma unroll
    for (int ii = 0; ii < 4; ii++) {
        int r = b * SEQ + i0 + ty * 4 + ii;
        int c = h * HDIM + tx * 4;
        float2 p0 = up2(acc[ii][0]), p1 = up2(acc[ii][1]);
        float4 o; o.x = p0.x; o.y = p0.y; o.z = p1.x; o.w = p1.y;
        *(float4*)(O + (size_t)r * DM + c) = o;
    }
}

// ---------------------------------------------------------------------------
extern "C" void kernel_launch(void* const* d_in, const int* in_sizes, int n_in,
                              void* d_out, int out_size)
{
    const int*   src    = (const int*)  d_in[0];
    const float* a_n    = (const float*)d_in[2];
    const float* b_n    = (const float*)d_in[3];
    const float* proj_w = (const float*)d_in[4];
    const float* proj_b = (const float*)d_in[5];
    const float* rule   = (const float*)d_in[6];
    const float* Wq     = (const float*)d_in[7];
    const float* Wk     = (const float*)d_in[8];
    const float* Wv     = (const float*)d_in[9];
    const float* Wo     = (const float*)d_in[10];
    const float* Wdown  = (const float*)d_in[11];
    const float* Wup_k  = (const float*)d_in[12];
    const float* Wup_v  = (const float*)d_in[13];
    const float* Wout   = (const float*)d_in[14];
    const float* bout   = (const float*)d_in[15];
    float* out = (float*)d_out;

    float *h, *kv, *qkv, *krvr, *lat, *four, *sc;
    __nv_bfloat16 *wbh, *wbl;
    cudaGetSymbolAddress((void**)&h,    g_h);
    cudaGetSymbolAddress((void**)&kv,   g_kv);
    cudaGetSymbolAddress((void**)&qkv,  g_qkv);
    cudaGetSymbolAddress((void**)&krvr, g_krvr);
    cudaGetSymbolAddress((void**)&lat,  g_lat);
    cudaGetSymbolAddress((void**)&four, g_four);
    cudaGetSymbolAddress((void**)&sc,   g_sc);
    cudaGetSymbolAddress((void**)&wbh,  g_wbh);
    cudaGetSymbolAddress((void**)&wbl,  g_wbl);

    cudaFuncSetAttribute(gemm_mma<4>, cudaFuncAttributeMaxDynamicSharedMemorySize, DSM4);
    cudaFuncSetAttribute(gemm_mma<2>, cudaFuncAttributeMaxDynamicSharedMemorySize, DSM2);

    // ---- transpose + split all weights into n-major [N][K] bf16 hi/lo ----
    // Fused groups concatenate along N (row offset = colOffset * K).
    {
        const dim3 b(32, 8);
        #define WSPLIT(W, K_, N_, BASE, ROWOFF) \
            wsplit_k<<<dim3((N_)/32, (K_)/32), b>>>(W, K_, N_, \
                wbh + (BASE) + (size_t)(ROWOFF)*(K_), wbl + (BASE) + (size_t)(ROWOFF)*(K_))
        WSPLIT(rule, DM, DM, OFF_RULE, 0);
        for (int l = 0; l < NL; l++) {
            size_t o = OFF_L(l);
            WSPLIT(Wq    + (size_t)l*DM*DM,   DM,   DM,   o + LOFF_QKV, 0);
            WSPLIT(Wk    + (size_t)l*DM*DM,   DM,   DM,   o + LOFF_QKV, DM);
            WSPLIT(Wv    + (size_t)l*DM*DM,   DM,   DM,   o + LOFF_QKV, 2*DM);
            WSPLIT(Wdown + (size_t)l*DM*DLAT, DM,   DLAT, o + LOFF_DOWN, 0);
            WSPLIT(Wup_k + (size_t)l*DLAT*DM, DLAT, DM,   o + LOFF_UP, 0);
            WSPLIT(Wup_v + (size_t)l*DLAT*DM, DLAT, DM,   o + LOFF_UP, DM);
            WSPLIT(Wo    + (size_t)l*DM*DM,   DM,   DM,   o + LOFF_WO, 0);
        }
        WSPLIT(Wout, DM, VOC, OFF_WOUT, 0);
        #undef WSPLIT
    }

    // ---- embedding ----
    fourier_k<<<(ROWS * NFR + 255) / 256, 256>>>(src, a_n, b_n, four);
    sgemm2_k<<<dim3(DM/128, ROWS/128), 256>>>(ROWS, DM, NFR, four, proj_w, proj_b, kv);
    gemm_mma<2><<<dim3(DM/128, ROWS/64), 256, DSM2>>>(
        ROWS, DM, DM, kv, nullptr, wbh + OFF_RULE, wbl + OFF_RULE, nullptr, h, DM);
    addpe_k<<<(ROWS * DM + 255) / 256, 256>>>(h);

    // ---- layers ----
    for (int l = 0; l < NL; l++) {
        size_t o = OFF_L(l);
        // fused QKV: [ROWS, 3072]
        gemm_mma<4><<<dim3(3*DM/128, ROWS/128), 256, DSM4>>>(
            ROWS, DM, DM, h, nullptr,
            wbh + o + LOFF_QKV, wbl + o + LOFF_QKV, nullptr, qkv, 3*DM);
        // down: A = k + v (strided views into qkv)
        gemm_mma<2><<<dim3(DLAT/128, ROWS/64), 256, DSM2>>>(
            ROWS, DM, 3*DM, qkv + DM, qkv + 2*DM,
            wbh + o + LOFF_DOWN, wbl + o + LOFF_DOWN, nullptr, lat, DLAT);
        // fused up: [ROWS, 2048]
        gemm_mma<4><<<dim3(2*DM/128, ROWS/128), 256, DSM4>>>(
            ROWS, DLAT, DLAT, lat, nullptr,
            wbh + o + LOFF_UP, wbl + o + LOFF_UP, nullptr, krvr, 2*DM);

        scores_k<<<dim3(SEQ/64, SEQ/64, BSZ*NH), 256>>>(qkv, 3*DM, krvr, 2*DM, sc);
        softmax_k<<<BSZ*NH*SEQ, 256>>>(sc);
        av_k<<<dim3(SEQ/64, BSZ*NH), 256>>>(sc, krvr + DM, 2*DM, kv);

        gemm_mma<2><<<dim3(DM/128, ROWS/64), 256, DSM2>>>(
            ROWS, DM, DM, kv, nullptr,
            wbh + o + LOFF_WO, wbl + o + LOFF_WO, nullptr, h, DM);
    }

    // ---- vocab projection ----
    gemm_mma<4><<<dim3(VOC/128, ROWS/128), 256, DSM4>>>(
        ROWS, DM, DM, h, nullptr,
        wbh + OFF_WOUT, wbl + OFF_WOUT, bout, out, VOC);
}

// round 9
// speedup vs baseline: 1.2840x; 1.2840x over previous
#include <cuda_runtime.h>
#include <cuda_bf16.h>
#include <math.h>
#include <stdint.h>

#define BSZ  2
#define SEQ  1024
#define DM   1024
#define NH   16
#define HDIM 64
#define NL   4
#define VOC  32000
#define NFR  50
#define DLAT 512
#define ROWS (BSZ*SEQ)   // 2048
#define KT   16

// ---------------- scratch (device globals; no allocation allowed) ----------
__device__ float g_h [ROWS*DM];
__device__ float g_q [ROWS*DM];
__device__ float g_k [ROWS*DM];
__device__ float g_v [ROWS*DM];
__device__ float g_kv[ROWS*DM];
__device__ float g_kr[ROWS*DM];
__device__ float g_vr[ROWS*DM];
__device__ float g_lat[ROWS*DLAT];
__device__ float g_four[ROWS*NFR];
__device__ float g_sc[(size_t)BSZ*NH*SEQ*SEQ];   // 134 MB score tensor

// transposed + split weights: [N][K] bf16, hi and lo halves
#define WSZ_DD   (1024*1024)
#define WSZ_HALF (512*1024)
#define LSTRIDE  (4*WSZ_DD + 3*WSZ_HALF)
#define OFF_RULE 0
#define OFF_L(l) ((size_t)WSZ_DD + (size_t)(l)*LSTRIDE)
#define OFF_WOUT ((size_t)WSZ_DD + 4*(size_t)LSTRIDE)
#define WTOT     (OFF_WOUT + (size_t)VOC*DM)
__device__ __align__(16) __nv_bfloat16 g_wbh[WTOT];
__device__ __align__(16) __nv_bfloat16 g_wbl[WTOT];

// ---------------- f32x2 packed helpers (Blackwell FFMA2) -------------------
__device__ __forceinline__ unsigned long long pk2(float lo, float hi) {
    unsigned long long r;
    asm("mov.b64 %0, {%1, %2};" : "=l"(r) : "f"(lo), "f"(hi));
    return r;
}
__device__ __forceinline__ unsigned long long ffma2(
    unsigned long long a, unsigned long long b, unsigned long long c) {
    unsigned long long d;
    asm("fma.rn.f32x2 %0, %1, %2, %3;" : "=l"(d) : "l"(a), "l"(b), "l"(c));
    return d;
}
__device__ __forceinline__ float2 up2(unsigned long long v) {
    float2 f;
    asm("mov.b64 {%0, %1}, %2;" : "=f"(f.x), "=f"(f.y) : "l"(v));
    return f;
}

// ---------------- misc helpers ---------------------------------------------
__device__ __forceinline__ uint32_t smem_to_u32(const void* p) {
    uint32_t a;
    asm("{ .reg .u64 t; cvta.to.shared.u64 t, %1; cvt.u32.u64 %0, t; }" : "=r"(a) : "l"(p));
    return a;
}
__device__ __forceinline__ uint32_t bfpack(float lo, float hi) {
    uint32_t r;
    asm("cvt.rn.bf16x2.f32 %0, %1, %2;" : "=r"(r) : "f"(hi), "f"(lo));
    return r;
}
__device__ __forceinline__ float bflo(uint32_t p) { return __uint_as_float(p << 16); }
__device__ __forceinline__ float bfhi(uint32_t p) { return __uint_as_float(p & 0xffff0000u); }
#define STS128(addr, a, b, c, d) \
    asm volatile("st.shared.v4.b32 [%0], {%1, %2, %3, %4};" \
        :: "r"(addr), "r"(a), "r"(b), "r"(c), "r"(d) : "memory")
#define LDSM_X4(r0, r1, r2, r3, addr) \
    asm volatile("ldmatrix.sync.aligned.m8n8.x4.shared.b16 {%0,%1,%2,%3}, [%4];" \
        : "=r"(r0), "=r"(r1), "=r"(r2), "=r"(r3) : "r"(addr))
#define LDSM_X2(r0, r1, addr) \
    asm volatile("ldmatrix.sync.aligned.m8n8.x2.shared.b16 {%0,%1}, [%2];" \
        : "=r"(r0), "=r"(r1) : "r"(addr))
#define LDSM_X2T(r0, r1, addr) \
    asm volatile("ldmatrix.sync.aligned.m8n8.x2.trans.shared.b16 {%0,%1}, [%2];" \
        : "=r"(r0), "=r"(r1) : "r"(addr))
#define MMA16816(d, a0, a1, a2, a3, b0, b1) \
    asm volatile("mma.sync.aligned.m16n8k16.row.col.f32.bf16.bf16.f32 " \
        "{%0,%1,%2,%3}, {%4,%5,%6,%7}, {%8,%9}, {%0,%1,%2,%3};" \
        : "+f"((d)[0]), "+f"((d)[1]), "+f"((d)[2]), "+f"((d)[3]) \
        : "r"(a0), "r"(a1), "r"(a2), "r"(a3), "r"(b0), "r"(b1))

// ================= weight transpose + bf16 split: W[K,N] -> T[N,K] =========
__global__ __launch_bounds__(256) void wsplit_k(
    const float* __restrict__ W, int K, int N,
    __nv_bfloat16* __restrict__ Th, __nv_bfloat16* __restrict__ Tl)
{
    __shared__ float t[32][33];
    const int k0 = blockIdx.y * 32, n0 = blockIdx.x * 32;
    const int tx = threadIdx.x, ty = threadIdx.y;   // (32,8)
#pragma unroll
    for (int i = 0; i < 4; i++)
        t[ty + 8 * i][tx] = W[(size_t)(k0 + ty + 8 * i) * N + n0 + tx];
    __syncthreads();
#pragma unroll
    for (int i = 0; i < 4; i++) {
        int n = n0 + ty + 8 * i, k = k0 + tx;
        float w = t[tx][ty + 8 * i];
        __nv_bfloat16 h = __float2bfloat16(w);
        float lo = w - __bfloat162float(h);
        Th[(size_t)n * K + k] = h;
        Tl[(size_t)n * K + k] = __float2bfloat16(lo);
    }
}

// ================= HMMA bf16-split GEMM (R5 proven version) ================
#define ASTR   40                       // bf16 elems per smem row (80 bytes)
#define TILEB  (128*80)
#define OAH    0
#define OAL    (TILEB)
#define OBH    (2*TILEB)
#define OBL    (3*TILEB)
#define BUFSTR (4*TILEB)
#define DSMG   (2*BUFSTR)               // 81920

__global__ __launch_bounds__(256) void gemm_mma(
    int M, int N, int K,
    const float* __restrict__ A,
    const __nv_bfloat16* __restrict__ Bh, const __nv_bfloat16* __restrict__ Bl,
    const float* __restrict__ bias, float* __restrict__ C)
{
    extern __shared__ char smem[];
    const uint32_t sb = smem_to_u32(smem);
    const int tid = threadIdx.x, lane = tid & 31, wid = tid >> 5;
    const int brow = blockIdx.y * 128, bcol = blockIdx.x * 128;
    const int wm = wid & 1, wn = wid >> 1;

    const int lrow = tid >> 1, lhalf = tid & 1;
    const float* Ap          = A  + (size_t)(brow + lrow) * K + lhalf * 16;
    const __nv_bfloat16* Bhp = Bh + (size_t)(bcol + lrow) * K + lhalf * 16;
    const __nv_bfloat16* Blp = Bl + (size_t)(bcol + lrow) * K + lhalf * 16;
    const uint32_t soff = (uint32_t)(lrow * ASTR + lhalf * 16) * 2;

    float acc[4][4][4];
#pragma unroll
    for (int i = 0; i < 4; i++)
#pragma unroll
        for (int j = 0; j < 4; j++)
#pragma unroll
            for (int e = 0; e < 4; e++) acc[i][j][e] = 0.f;

    float4 pa[4]; uint4 pbh[2], pbl[2];

#define LOADG(k0) do { \
    pa[0] = *(const float4*)(Ap + (k0));      pa[1] = *(const float4*)(Ap + (k0) + 4); \
    pa[2] = *(const float4*)(Ap + (k0) + 8);  pa[3] = *(const float4*)(Ap + (k0) + 12); \
    pbh[0] = *(const uint4*)(Bhp + (k0));     pbh[1] = *(const uint4*)(Bhp + (k0) + 8); \
    pbl[0] = *(const uint4*)(Blp + (k0));     pbl[1] = *(const uint4*)(Blp + (k0) + 8); \
} while (0)

#define STOREBUF(b) do { \
    uint32_t hh[8], ll[8]; \
    _Pragma("unroll") \
    for (int i = 0; i < 4; i++) { \
        float4 x = pa[i]; \
        uint32_t h0 = bfpack(x.x, x.y), h1 = bfpack(x.z, x.w); \
        uint32_t l0 = bfpack(x.x - bflo(h0), x.y - bfhi(h0)); \
        uint32_t l1 = bfpack(x.z - bflo(h1), x.w - bfhi(h1)); \
        hh[2*i] = h0; hh[2*i+1] = h1; ll[2*i] = l0; ll[2*i+1] = l1; \
    } \
    uint32_t base_ = sb + (uint32_t)(b) * BUFSTR; \
    STS128(base_ + OAH + soff,      hh[0], hh[1], hh[2], hh[3]); \
    STS128(base_ + OAH + soff + 16, hh[4], hh[5], hh[6], hh[7]); \
    STS128(base_ + OAL + soff,      ll[0], ll[1], ll[2], ll[3]); \
    STS128(base_ + OAL + soff + 16, ll[4], ll[5], ll[6], ll[7]); \
    STS128(base_ + OBH + soff,      pbh[0].x, pbh[0].y, pbh[0].z, pbh[0].w); \
    STS128(base_ + OBH + soff + 16, pbh[1].x, pbh[1].y, pbh[1].z, pbh[1].w); \
    STS128(base_ + OBL + soff,      pbl[0].x, pbl[0].y, pbl[0].z, pbl[0].w); \
    STS128(base_ + OBL + soff + 16, pbl[1].x, pbl[1].y, pbl[1].z, pbl[1].w); \
} while (0)

    const int nchunk = K / 32;
    LOADG(0);
    STOREBUF(0);
    __syncthreads();

    const uint32_t arow = (uint32_t)(wm * 64 + (lane & 15));
    const uint32_t acol = (uint32_t)((lane >> 4) * 8);
    const uint32_t brw  = (uint32_t)(wn * 32 + (lane & 7));
    const uint32_t bcl  = (uint32_t)(((lane >> 3) & 1) * 8);

    int buf = 0;
    for (int ck = 0; ck < nchunk; ck++) {
        if (ck + 1 < nchunk) LOADG((ck + 1) * 32);

        const uint32_t base = sb + (uint32_t)buf * BUFSTR;
#pragma unroll
        for (int ks = 0; ks < 2; ks++) {
            uint32_t ah[4][4], al[4][4];
#pragma unroll
            for (int mt = 0; mt < 4; mt++) {
                uint32_t aoff = ((arow + mt * 16) * ASTR + acol + ks * 16) * 2;
                LDSM_X4(ah[mt][0], ah[mt][1], ah[mt][2], ah[mt][3], base + OAH + aoff);
                LDSM_X4(al[mt][0], al[mt][1], al[mt][2], al[mt][3], base + OAL + aoff);
            }
#pragma unroll
            for (int nt = 0; nt < 4; nt++) {
                uint32_t boff = ((brw + nt * 8) * ASTR + bcl + ks * 16) * 2;
                uint32_t bh0, bh1, bl0, bl1;
                LDSM_X2(bh0, bh1, base + OBH + boff);
                LDSM_X2(bl0, bl1, base + OBL + boff);
#pragma unroll
                for (int mt = 0; mt < 4; mt++) {
                    MMA16816(acc[mt][nt], ah[mt][0], ah[mt][1], ah[mt][2], ah[mt][3], bh0, bh1);
                    MMA16816(acc[mt][nt], ah[mt][0], ah[mt][1], ah[mt][2], ah[mt][3], bl0, bl1);
                    MMA16816(acc[mt][nt], al[mt][0], al[mt][1], al[mt][2], al[mt][3], bh0, bh1);
                }
            }
        }
        if (ck + 1 < nchunk) STOREBUF(buf ^ 1);
        __syncthreads();
        buf ^= 1;
    }

#pragma unroll
    for (int mt = 0; mt < 4; mt++) {
        int r0 = brow + wm * 64 + mt * 16 + (lane >> 2);
#pragma unroll
        for (int nt = 0; nt < 4; nt++) {
            int c = bcol + wn * 32 + nt * 8 + (lane & 3) * 2;
            float bx = 0.f, by = 0.f;
            if (bias) { bx = bias[c]; by = bias[c + 1]; }
            float2 o0, o1;
            o0.x = acc[mt][nt][0] + bx; o0.y = acc[mt][nt][1] + by;
            o1.x = acc[mt][nt][2] + bx; o1.y = acc[mt][nt][3] + by;
            *(float2*)(C + (size_t)r0 * N + c)       = o0;
            *(float2*)(C + (size_t)(r0 + 8) * N + c) = o1;
        }
    }
#undef LOADG
#undef STOREBUF
}

// ================= HMMA split attention: scores ============================
// Sc[bh, i, j] = (Q_bh[i,:] . K_bh[j,:]) * scale * exp(-0.01|i-j|)
// 128x128 tile, K=64 (head dim), Q/K split to bf16 hi/lo in smem.
#define SCTAB 40960
#define DSMS  (40960 + 1024)

__global__ __launch_bounds__(256) void scores_hmma(
    const float* __restrict__ Q, const float* __restrict__ Kc, float* __restrict__ Sc)
{
    extern __shared__ char smem[];
    const uint32_t sb = smem_to_u32(smem);
    float* tab = (float*)(smem + SCTAB);
    const int OQH = 0, OQL = 10240, OKH = 20480, OKL = 30720;
    const int tid = threadIdx.x, lane = tid & 31, wid = tid >> 5;
    const int bh = blockIdx.z, b = bh >> 4, h = bh & 15;
    const int i0 = blockIdx.y * 128, j0 = blockIdx.x * 128;
    const int wm = wid & 1, wn = wid >> 1;

    tab[tid] = __expf(-0.01f * fabsf((float)(i0 - j0 + tid - 128)));

    const int lrow = tid >> 1, lseg = tid & 1;
    {
        const float* qp = Q  + (size_t)(b * SEQ + i0 + lrow) * DM + h * HDIM + lseg * 32;
        const float* kp = Kc + (size_t)(b * SEQ + j0 + lrow) * DM + h * HDIM + lseg * 32;
        const uint32_t off = (uint32_t)(lrow * ASTR + lseg * 32) * 2;
#pragma unroll
        for (int half = 0; half < 2; half++) {
            const float* p = half ? kp : qp;
            const uint32_t oh = half ? OKH : OQH, ol = half ? OKL : OQL;
            uint32_t hh[16], ll[16];
#pragma unroll
            for (int i = 0; i < 8; i++) {
                float4 x = *(const float4*)(p + i * 4);
                uint32_t h0 = bfpack(x.x, x.y), h1 = bfpack(x.z, x.w);
                hh[2*i] = h0; hh[2*i+1] = h1;
                ll[2*i]   = bfpack(x.x - bflo(h0), x.y - bfhi(h0));
                ll[2*i+1] = bfpack(x.z - bflo(h1), x.w - bfhi(h1));
            }
#pragma unroll
            for (int i = 0; i < 4; i++) {
                STS128(sb + oh + off + i * 16, hh[4*i], hh[4*i+1], hh[4*i+2], hh[4*i+3]);
                STS128(sb + ol + off + i * 16, ll[4*i], ll[4*i+1], ll[4*i+2], ll[4*i+3]);
            }
        }
    }
    __syncthreads();

    float acc[4][4][4];
#pragma unroll
    for (int i = 0; i < 4; i++)
#pragma unroll
        for (int j = 0; j < 4; j++)
#pragma unroll
            for (int e = 0; e < 4; e++) acc[i][j][e] = 0.f;

    const uint32_t arow = (uint32_t)(wm * 64 + (lane & 15));
    const uint32_t acol = (uint32_t)((lane >> 4) * 8);
    const uint32_t brw  = (uint32_t)(wn * 32 + (lane & 7));
    const uint32_t bcl  = (uint32_t)(((lane >> 3) & 1) * 8);

#pragma unroll
    for (int ks = 0; ks < 4; ks++) {
        uint32_t ah[4][4], al[4][4];
#pragma unroll
        for (int mt = 0; mt < 4; mt++) {
            uint32_t aoff = ((arow + mt * 16) * ASTR + acol + ks * 16) * 2;
            LDSM_X4(ah[mt][0], ah[mt][1], ah[mt][2], ah[mt][3], sb + OQH + aoff);
            LDSM_X4(al[mt][0], al[mt][1], al[mt][2], al[mt][3], sb + OQL + aoff);
        }
#pragma unroll
        for (int nt = 0; nt < 4; nt++) {
            uint32_t boff = ((brw + nt * 8) * ASTR + bcl + ks * 16) * 2;
            uint32_t bh0, bh1, bl0, bl1;
            LDSM_X2(bh0, bh1, sb + OKH + boff);
            LDSM_X2(bl0, bl1, sb + OKL + boff);
#pragma unroll
            for (int mt = 0; mt < 4; mt++) {
                MMA16816(acc[mt][nt], ah[mt][0], ah[mt][1], ah[mt][2], ah[mt][3], bh0, bh1);
                MMA16816(acc[mt][nt], ah[mt][0], ah[mt][1], ah[mt][2], ah[mt][3], bl0, bl1);
                MMA16816(acc[mt][nt], al[mt][0], al[mt][1], al[mt][2], al[mt][3], bh0, bh1);
            }
        }
    }

    const float scale = 0.03125f;
#pragma unroll
    for (int mt = 0; mt < 4; mt++) {
        int ri = wm * 64 + mt * 16 + (lane >> 2);
#pragma unroll
        for (int nt = 0; nt < 4; nt++) {
            int cj = wn * 32 + nt * 8 + (lane & 3) * 2;
            int d0 = ri - cj + 128;
            float2 o0, o1;
            o0.x = acc[mt][nt][0] * scale * tab[d0];
            o0.y = acc[mt][nt][1] * scale * tab[d0 - 1];
            o1.x = acc[mt][nt][2] * scale * tab[d0 + 8];
            o1.y = acc[mt][nt][3] * scale * tab[d0 + 7];
            *(float2*)(Sc + ((size_t)bh * SEQ + i0 + ri) * SEQ + j0 + cj)       = o0;
            *(float2*)(Sc + ((size_t)bh * SEQ + i0 + ri + 8) * SEQ + j0 + cj)   = o1;
        }
    }
}

// ================= HMMA split attention: O = P @ V =========================
// 128 i-rows x 64 d-cols per CTA, K = SEQ over j in 32-chunks, double-buffered.
// P is A-operand (row-major); V stored k-major [j][d] and consumed via
// ldmatrix.trans (R6-validated B path).
#define VSTR  72                          // elems (144 B) per V smem row
#define OPH2  0
#define OPL2  10240
#define OVH2  20480
#define OVL2  25088
#define BUF2  29696
#define DSMA  (2*BUF2)                    // 59392

__global__ __launch_bounds__(256) void av_hmma(
    const float* __restrict__ P, const float* __restrict__ V, float* __restrict__ O)
{
    extern __shared__ char smem[];
    const uint32_t sb = smem_to_u32(smem);
    const int tid = threadIdx.x, lane = tid & 31, wid = tid >> 5;
    const int bh = blockIdx.y, b = bh >> 4, h = bh & 15;
    const int i0 = blockIdx.x * 128;
    const int wm = wid & 3, wn = wid >> 2;   // 4 x 2 warps: m 32, n 32

    const int lrow = tid >> 1, lseg = tid & 1;
    const float* Pp = P + ((size_t)bh * SEQ + i0 + lrow) * SEQ + lseg * 16;
    const uint32_t poff = (uint32_t)(lrow * ASTR + lseg * 16) * 2;

    const int vj = tid >> 3, vd = (tid & 7) * 8;
    const float* Vp = V + (size_t)(b * SEQ + vj) * DM + h * HDIM + vd;
    const uint32_t voff = (uint32_t)(vj * VSTR + vd) * 2;

    float acc[2][4][4];
#pragma unroll
    for (int i = 0; i < 2; i++)
#pragma unroll
        for (int j = 0; j < 4; j++)
#pragma unroll
            for (int e = 0; e < 4; e++) acc[i][j][e] = 0.f;

    float4 pa[4], pv[2];

#define LOADG2(k0) do { \
    pa[0] = *(const float4*)(Pp + (k0));      pa[1] = *(const float4*)(Pp + (k0) + 4); \
    pa[2] = *(const float4*)(Pp + (k0) + 8);  pa[3] = *(const float4*)(Pp + (k0) + 12); \
    pv[0] = *(const float4*)(Vp + (size_t)(k0) * DM); \
    pv[1] = *(const float4*)(Vp + (size_t)(k0) * DM + 4); \
} while (0)

#define STOREBUF2(bf) do { \
    uint32_t hh[8], ll[8]; \
    _Pragma("unroll") \
    for (int i = 0; i < 4; i++) { \
        float4 x = pa[i]; \
        uint32_t h0 = bfpack(x.x, x.y), h1 = bfpack(x.z, x.w); \
        hh[2*i] = h0; hh[2*i+1] = h1; \
        ll[2*i]   = bfpack(x.x - bflo(h0), x.y - bfhi(h0)); \
        ll[2*i+1] = bfpack(x.z - bflo(h1), x.w - bfhi(h1)); \
    } \
    uint32_t vh[4], vl[4]; \
    _Pragma("unroll") \
    for (int i = 0; i < 2; i++) { \
        float4 x = pv[i]; \
        uint32_t h0 = bfpack(x.x, x.y), h1 = bfpack(x.z, x.w); \
        vh[2*i] = h0; vh[2*i+1] = h1; \
        vl[2*i]   = bfpack(x.x - bflo(h0), x.y - bfhi(h0)); \
        vl[2*i+1] = bfpack(x.z - bflo(h1), x.w - bfhi(h1)); \
    } \
    uint32_t base_ = sb + (uint32_t)(bf) * BUF2; \
    STS128(base_ + OPH2 + poff,      hh[0], hh[1], hh[2], hh[3]); \
    STS128(base_ + OPH2 + poff + 16, hh[4], hh[5], hh[6], hh[7]); \
    STS128(base_ + OPL2 + poff,      ll[0], ll[1], ll[2], ll[3]); \
    STS128(base_ + OPL2 + poff + 16, ll[4], ll[5], ll[6], ll[7]); \
    STS128(base_ + OVH2 + voff, vh[0], vh[1], vh[2], vh[3]); \
    STS128(base_ + OVL2 + voff, vl[0], vl[1], vl[2], vl[3]); \
} while (0)

    const int nchunk = SEQ / 32;
    LOADG2(0);
    STOREBUF2(0);
    __syncthreads();

    const uint32_t arow = (uint32_t)(wm * 32 + (lane & 15));
    const uint32_t acol = (uint32_t)((lane >> 4) * 8);
    const uint32_t kl   = (uint32_t)(lane & 15);

    int buf = 0;
    for (int ck = 0; ck < nchunk; ck++) {
        if (ck + 1 < nchunk) LOADG2((ck + 1) * 32);

        const uint32_t base = sb + (uint32_t)buf * BUF2;
#pragma unroll
        for (int ks = 0; ks < 2; ks++) {
            uint32_t ah[2][4], al[2][4];
#pragma unroll
            for (int mt = 0; mt < 2; mt++) {
                uint32_t aoff = ((arow + mt * 16) * ASTR + acol + ks * 16) * 2;
                LDSM_X4(ah[mt][0], ah[mt][1], ah[mt][2], ah[mt][3], base + OPH2 + aoff);
                LDSM_X4(al[mt][0], al[mt][1], al[mt][2], al[mt][3], base + OPL2 + aoff);
            }
#pragma unroll
            for (int nt = 0; nt < 4; nt++) {
                uint32_t boff = ((ks * 16 + kl) * VSTR + wn * 32 + nt * 8) * 2;
                uint32_t bh0, bh1, bl0, bl1;
                LDSM_X2T(bh0, bh1, base + OVH2 + boff);
                LDSM_X2T(bl0, bl1, base + OVL2 + boff);
#pragma unroll
                for (int mt = 0; mt < 2; mt++) {
                    MMA16816(acc[mt][nt], ah[mt][0], ah[mt][1], ah[mt][2], ah[mt][3], bh0, bh1);
                    MMA16816(acc[mt][nt], ah[mt][0], ah[mt][1], ah[mt][2], ah[mt][3], bl0, bl1);
                    MMA16816(acc[mt][nt], al[mt][0], al[mt][1], al[mt][2], al[mt][3], bh0, bh1);
                }
            }
        }
        if (ck + 1 < nchunk) STOREBUF2(buf ^ 1);
        __syncthreads();
        buf ^= 1;
    }

#pragma unroll
    for (int mt = 0; mt < 2; mt++) {
        int r0 = i0 + wm * 32 + mt * 16 + (lane >> 2);
#pragma unroll
        for (int nt = 0; nt < 4; nt++) {
            int c = h * HDIM + wn * 32 + nt * 8 + (lane & 3) * 2;
            float2 o0, o1;
            o0.x = acc[mt][nt][0]; o0.y = acc[mt][nt][1];
            o1.x = acc[mt][nt][2]; o1.y = acc[mt][nt][3];
            *(float2*)(O + (size_t)(b * SEQ + r0) * DM + c)       = o0;
            *(float2*)(O + (size_t)(b * SEQ + r0 + 8) * DM + c)   = o1;
        }
    }
#undef LOADG2
#undef STOREBUF2
}

// ---------------- FFMA2 SGEMM (kept for the K=50 embedding GEMM) -----------
__global__ __launch_bounds__(256) void sgemm2_k(
    int M, int N, int K,
    const float* __restrict__ A, const float* __restrict__ B,
    const float* __restrict__ bias, float* __restrict__ C)
{
    __shared__ __align__(16) float As[KT][128];
    __shared__ __align__(16) float Bs[KT][128];
    const int tid  = threadIdx.x;
    const int brow = blockIdx.y * 128;
    const int bcol = blockIdx.x * 128;
    const int ty = tid >> 4, tx = tid & 15;
    const int ar = tid >> 1, aks = (tid & 1) * 8;

    unsigned long long acc[8][4];
#pragma unroll
    for (int i = 0; i < 8; i++)
#pragma unroll
        for (int j = 0; j < 4; j++) acc[i][j] = 0ULL;

    for (int k0 = 0; k0 < K; k0 += KT) {
#pragma unroll
        for (int i = 0; i < 8; i++) {
            int kk = aks + i;
            As[kk][ar] = (k0 + kk < K) ? A[(size_t)(brow + ar) * K + k0 + kk] : 0.f;
        }
#pragma unroll
        for (int p = 0; p < 2; p++) {
            int id = p * 256 + tid;
            int kk = id >> 5, c4 = (id & 31) * 4;
            float4 bv = make_float4(0.f, 0.f, 0.f, 0.f);
            if (k0 + kk < K) bv = *(const float4*)(B + (size_t)(k0 + kk) * N + bcol + c4);
            *(float4*)&Bs[kk][c4] = bv;
        }
        __syncthreads();
#pragma unroll
        for (int kk = 0; kk < KT; kk++) {
            float4 a0 = *(const float4*)&As[kk][ty * 4];
            float4 a1 = *(const float4*)&As[kk][64 + ty * 4];
            float4 b0 = *(const float4*)&Bs[kk][tx * 4];
            float4 b1 = *(const float4*)&Bs[kk][64 + tx * 4];
            unsigned long long rb[4] = { pk2(b0.x, b0.y), pk2(b0.z, b0.w),
                                         pk2(b1.x, b1.y), pk2(b1.z, b1.w) };
            float ra[8] = { a0.x, a0.y, a0.z, a0.w, a1.x, a1.y, a1.z, a1.w };
#pragma unroll
            for (int i = 0; i < 8; i++) {
                unsigned long long ad = pk2(ra[i], ra[i]);
#pragma unroll
                for (int j = 0; j < 4; j++) acc[i][j] = ffma2(ad, rb[j], acc[i][j]);
            }
        }
        __syncthreads();
    }
#pragma unroll
    for (int ih = 0; ih < 2; ih++)
#pragma unroll
    for (int ii = 0; ii < 4; ii++) {
        int i = ih * 4 + ii;
        int r = brow + ih * 64 + ty * 4 + ii;
#pragma unroll
        for (int jh = 0; jh < 2; jh++) {
            int c = bcol + jh * 64 + tx * 4;
            float2 p0 = up2(acc[i][jh * 2]);
            float2 p1 = up2(acc[i][jh * 2 + 1]);
            float4 o; o.x = p0.x; o.y = p0.y; o.z = p1.x; o.w = p1.y;
            if (bias) { o.x += bias[c]; o.y += bias[c+1]; o.z += bias[c+2]; o.w += bias[c+3]; }
            *(float4*)(C + (size_t)r * N + c) = o;
        }
    }
}

// ---------------- Fourier token features -----------------------------------
__global__ void fourier_k(const int* __restrict__ src, const float* __restrict__ a_n,
                          const float* __restrict__ b_n, float* __restrict__ F)
{
    int idx = blockIdx.x * blockDim.x + threadIdx.x;
    if (idx >= ROWS * NFR) return;
    int bs = idx / NFR, n = idx % NFR;
    int tok = src[bs];
    float x   = (float)tok * (1.0f / (float)VOC);
    float ang = 6.28318530717958647692f * (float)(n + 1) * x;
    F[idx] = a_n[tok * NFR + n] * cosf(ang) + b_n[tok * NFR + n] * sinf(ang);
}

// ---------------- h += sinusoidal PE ---------------------------------------
__global__ void addpe_k(float* __restrict__ h)
{
    int idx = blockIdx.x * blockDim.x + threadIdx.x;
    if (idx >= ROWS * DM) return;
    int d = idx & (DM - 1);
    int s = (idx / DM) & (SEQ - 1);
    float div = expf(-(float)(d & ~1) * 8.99447301948846e-3f);
    float ang = (float)s * div;
    h[idx] += (d & 1) ? cosf(ang) : sinf(ang);
}

__global__ void add_k(const float* __restrict__ a, const float* __restrict__ b,
                      float* __restrict__ c, int n)
{
    int i = blockIdx.x * blockDim.x + threadIdx.x;
    if (i < n) c[i] = a[i] + b[i];
}

// ---------------- row softmax ----------------------------------------------
__global__ __launch_bounds__(256) void softmax_k(float* __restrict__ Sc)
{
    __shared__ float red[256];
    float* p = Sc + (size_t)blockIdx.x * SEQ;
    const int t = threadIdx.x;
    float v0 = p[t], v1 = p[t + 256], v2 = p[t + 512], v3 = p[t + 768];
    float mx = fmaxf(fmaxf(v0, v1), fmaxf(v2, v3));
    red[t] = mx; __syncthreads();
    for (int s = 128; s > 0; s >>= 1) { if (t < s) red[t] = fmaxf(red[t], red[t + s]); __syncthreads(); }
    mx = red[0]; __syncthreads();
    v0 = __expf(v0 - mx); v1 = __expf(v1 - mx); v2 = __expf(v2 - mx); v3 = __expf(v3 - mx);
    float sm = v0 + v1 + v2 + v3;
    red[t] = sm; __syncthreads();
    for (int s = 128; s > 0; s >>= 1) { if (t < s) red[t] += red[t + s]; __syncthreads(); }
    float inv = 1.0f / red[0];
    p[t] = v0 * inv; p[t + 256] = v1 * inv; p[t + 512] = v2 * inv; p[t + 768] = v3 * inv;
}

// ---------------------------------------------------------------------------
extern "C" void kernel_launch(void* const* d_in, const int* in_sizes, int n_in,
                              void* d_out, int out_size)
{
    const int*   src    = (const int*)  d_in[0];
    const float* a_n    = (const float*)d_in[2];
    const float* b_n    = (const float*)d_in[3];
    const float* proj_w = (const float*)d_in[4];
    const float* proj_b = (const float*)d_in[5];
    const float* rule   = (const float*)d_in[6];
    const float* Wq     = (const float*)d_in[7];
    const float* Wk     = (const float*)d_in[8];
    const float* Wv     = (const float*)d_in[9];
    const float* Wo     = (const float*)d_in[10];
    const float* Wdown  = (const float*)d_in[11];
    const float* Wup_k  = (const float*)d_in[12];
    const float* Wup_v  = (const float*)d_in[13];
    const float* Wout   = (const float*)d_in[14];
    const float* bout   = (const float*)d_in[15];
    float* out = (float*)d_out;

    float *h, *q, *k, *v, *kv, *kr, *vr, *lat, *four, *sc;
    __nv_bfloat16 *wbh, *wbl;
    cudaGetSymbolAddress((void**)&h,    g_h);
    cudaGetSymbolAddress((void**)&q,    g_q);
    cudaGetSymbolAddress((void**)&k,    g_k);
    cudaGetSymbolAddress((void**)&v,    g_v);
    cudaGetSymbolAddress((void**)&kv,   g_kv);
    cudaGetSymbolAddress((void**)&kr,   g_kr);
    cudaGetSymbolAddress((void**)&vr,   g_vr);
    cudaGetSymbolAddress((void**)&lat,  g_lat);
    cudaGetSymbolAddress((void**)&four, g_four);
    cudaGetSymbolAddress((void**)&sc,   g_sc);
    cudaGetSymbolAddress((void**)&wbh,  g_wbh);
    cudaGetSymbolAddress((void**)&wbl,  g_wbl);

    cudaFuncSetAttribute(gemm_mma,   cudaFuncAttributeMaxDynamicSharedMemorySize, DSMG);
    cudaFuncSetAttribute(scores_hmma, cudaFuncAttributeMaxDynamicSharedMemorySize, DSMS);
    cudaFuncSetAttribute(av_hmma,    cudaFuncAttributeMaxDynamicSharedMemorySize, DSMA);

    // ---- transpose + split all weights into [N,K] bf16 hi/lo ----
    {
        const dim3 b(32, 8);
        wsplit_k<<<dim3(DM/32, DM/32), b>>>(rule, DM, DM, wbh + OFF_RULE, wbl + OFF_RULE);
        for (int l = 0; l < NL; l++) {
            size_t o = OFF_L(l);
            wsplit_k<<<dim3(DM/32, DM/32), b>>>(Wq + (size_t)l*DM*DM, DM, DM, wbh+o, wbl+o);
            wsplit_k<<<dim3(DM/32, DM/32), b>>>(Wk + (size_t)l*DM*DM, DM, DM, wbh+o+WSZ_DD, wbl+o+WSZ_DD);
            wsplit_k<<<dim3(DM/32, DM/32), b>>>(Wv + (size_t)l*DM*DM, DM, DM, wbh+o+2*WSZ_DD, wbl+o+2*WSZ_DD);
            wsplit_k<<<dim3(DM/32, DM/32), b>>>(Wo + (size_t)l*DM*DM, DM, DM, wbh+o+3*WSZ_DD, wbl+o+3*WSZ_DD);
            wsplit_k<<<dim3(DLAT/32, DM/32), b>>>(Wdown + (size_t)l*DM*DLAT, DM, DLAT,
                                                  wbh+o+4*WSZ_DD, wbl+o+4*WSZ_DD);
            wsplit_k<<<dim3(DM/32, DLAT/32), b>>>(Wup_k + (size_t)l*DLAT*DM, DLAT, DM,
                                                  wbh+o+4*WSZ_DD+WSZ_HALF, wbl+o+4*WSZ_DD+WSZ_HALF);
            wsplit_k<<<dim3(DM/32, DLAT/32), b>>>(Wup_v + (size_t)l*DLAT*DM, DLAT, DM,
                                                  wbh+o+4*WSZ_DD+2*WSZ_HALF, wbl+o+4*WSZ_DD+2*WSZ_HALF);
        }
        wsplit_k<<<dim3(VOC/32, DM/32), b>>>(Wout, DM, VOC, wbh + OFF_WOUT, wbl + OFF_WOUT);
    }

    const dim3 g_d  (DM   / 128, ROWS / 128);
    const dim3 g_dl (DLAT / 128, ROWS / 128);
    const dim3 g_voc(VOC  / 128, ROWS / 128);

    // ---- embedding ----
    fourier_k<<<(ROWS * NFR + 255) / 256, 256>>>(src, a_n, b_n, four);
    sgemm2_k<<<g_d, 256>>>(ROWS, DM, NFR, four, proj_w, proj_b, q);
    gemm_mma<<<g_d, 256, DSMG>>>(ROWS, DM, DM, q, wbh + OFF_RULE, wbl + OFF_RULE, nullptr, h);
    addpe_k<<<(ROWS * DM + 255) / 256, 256>>>(h);

    // ---- layers ----
    for (int l = 0; l < NL; l++) {
        size_t o = OFF_L(l);
        const __nv_bfloat16 *qh = wbh+o,             *ql = wbl+o;
        const __nv_bfloat16 *kh = wbh+o+WSZ_DD,      *kl = wbl+o+WSZ_DD;
        const __nv_bfloat16 *vh = wbh+o+2*WSZ_DD,    *vl = wbl+o+2*WSZ_DD;
        const __nv_bfloat16 *oh = wbh+o+3*WSZ_DD,    *ol = wbl+o+3*WSZ_DD;
        const __nv_bfloat16 *dh = wbh+o+4*WSZ_DD,    *dl = wbl+o+4*WSZ_DD;
        const __nv_bfloat16 *ukh= wbh+o+4*WSZ_DD+WSZ_HALF,   *ukl= wbl+o+4*WSZ_DD+WSZ_HALF;
        const __nv_bfloat16 *uvh= wbh+o+4*WSZ_DD+2*WSZ_HALF, *uvl= wbl+o+4*WSZ_DD+2*WSZ_HALF;

        gemm_mma<<<g_d, 256, DSMG>>>(ROWS, DM, DM, h, qh, ql, nullptr, q);
        gemm_mma<<<g_d, 256, DSMG>>>(ROWS, DM, DM, h, kh, kl, nullptr, k);
        gemm_mma<<<g_d, 256, DSMG>>>(ROWS, DM, DM, h, vh, vl, nullptr, v);
        add_k<<<(ROWS * DM + 255) / 256, 256>>>(k, v, kv, ROWS * DM);
        gemm_mma<<<g_dl, 256, DSMG>>>(ROWS, DLAT, DM, kv, dh, dl, nullptr, lat);
        gemm_mma<<<g_d, 256, DSMG>>>(ROWS, DM, DLAT, lat, ukh, ukl, nullptr, kr);
        gemm_mma<<<g_d, 256, DSMG>>>(ROWS, DM, DLAT, lat, uvh, uvl, nullptr, vr);

        scores_hmma<<<dim3(SEQ/128, SEQ/128, BSZ*NH), 256, DSMS>>>(q, kr, sc);
        softmax_k<<<BSZ*NH*SEQ, 256>>>(sc);
        av_hmma<<<dim3(SEQ/128, BSZ*NH), 256, DSMA>>>(sc, vr, kv);

        gemm_mma<<<g_d, 256, DSMG>>>(ROWS, DM, DM, kv, oh, ol, nullptr, h);
    }

    // ---- vocab projection ----
    gemm_mma<<<g_voc, 256, DSMG>>>(ROWS, VOC, DM, h, wbh + OFF_WOUT, wbl + OFF_WOUT, bout, out);
}